// round 15
// baseline (speedup 1.0000x reference)
#include <cuda_runtime.h>

#define B_    16
#define C_    64
#define COUT_ 64
#define L_    16384
#define K_    3
#define CK_   (K_ * C_)   // 192
#define TLB_  64          // l per block (offmsk kernel)
#define TLM_  32          // l per block (main kernel)
#define NT_   256
#define PSTR_ 66          // partial staging stride over o (even)

// scratch (no allocations allowed)
__device__ float g_wt[CK_ * COUT_];       // [ck][o], ck = k*64 + c
__device__ float g_off[B_ * K_ * L_];     // [b][k][l]
__device__ float g_msk[B_ * K_ * L_];     // [b][k][l]

// ---------------- f32x2 helpers ----------------
__device__ __forceinline__ void unpack2(unsigned long long v, float& lo, float& hi) {
    asm("mov.b64 {%0, %1}, %2;" : "=f"(lo), "=f"(hi) : "l"(v));
}
__device__ __forceinline__ void fma2(unsigned long long& d, unsigned long long a,
                                     unsigned long long b) {
    asm("fma.rn.f32x2 %0, %1, %2, %0;" : "+l"(d) : "l"(a), "l"(b));
}

// ================= kernel A: weight transpose =================
__global__ void wt_kernel(const float* __restrict__ weight) {
    int i = blockIdx.x * blockDim.x + threadIdx.x;
    if (i < CK_ * COUT_) {
        int o  = i & 63;
        int ck = i >> 6;
        int c  = ck & 63;
        int k  = ck >> 6;
        g_wt[i] = weight[o * CK_ + c * K_ + k];
    }
}

// ================= kernel B: offset / mask branches =================
// dynamic smem: 8192 floats (32 KB): dwAT [c][li], dwBT [c][li]
__global__ __launch_bounds__(NT_, 4) void offmsk_kernel(
    const float* __restrict__ x,
    const float* __restrict__ wodw, const float* __restrict__ bodw,
    const float* __restrict__ wopw, const float* __restrict__ bopw,
    const float* __restrict__ wmdw, const float* __restrict__ bmdw,
    const float* __restrict__ wmpw, const float* __restrict__ bmpw)
{
    extern __shared__ float smem[];
    float* dwAT = smem;           // 4096  [c][li]
    float* dwBT = smem + 4096;    // 4096  [c][li]

    __shared__ float s_wdwA[448], s_wdwB[448];
    __shared__ float s_bdwA[64],  s_bdwB[64];
    __shared__ float s_wpwA[192], s_wpwB[192];
    __shared__ float s_bpwA[4],   s_bpwB[4];

    const int tid = threadIdx.x;
    const int b   = blockIdx.y;
    const int l0  = blockIdx.x * TLB_;
    const float* xb = x + (long)b * 64 * L_;

    #pragma unroll
    for (int i = tid; i < 448; i += NT_) { s_wdwA[i] = wodw[i]; s_wdwB[i] = wmdw[i]; }
    if (tid < 64)  { s_bdwA[tid] = bodw[tid]; s_bdwB[tid] = bmdw[tid]; }
    if (tid < 192) { s_wpwA[tid] = wopw[tid]; s_wpwB[tid] = wmpw[tid]; }
    if (tid < 3)   { s_bpwA[tid] = bopw[tid]; s_bpwB[tid] = bmpw[tid]; }
    __syncthreads();

    // depthwise 7-tap conv, register-blocked (x read once)
    {
        const int lg    = tid & 15;
        const int c0    = tid >> 4;
        const int lbase = lg * 4;
        const bool safe = (l0 + lbase - 4 >= 0) && (l0 + lbase + 8 <= L_);
        #pragma unroll
        for (int it = 0; it < 4; ++it) {
            int c = it * 16 + c0;
            const float* xr = xb + c * L_;
            float xw[12];
            if (safe) {
                const float4* x4 = (const float4*)(xr + l0 + lbase - 4);
                float4 f0 = x4[0], f1 = x4[1], f2 = x4[2];
                xw[0]=f0.x; xw[1]=f0.y; xw[2]=f0.z; xw[3]=f0.w;
                xw[4]=f1.x; xw[5]=f1.y; xw[6]=f1.z; xw[7]=f1.w;
                xw[8]=f2.x; xw[9]=f2.y; xw[10]=f2.z; xw[11]=f2.w;
            } else {
                #pragma unroll
                for (int j = 0; j < 12; ++j) {
                    int idx = l0 + lbase - 4 + j;
                    xw[j] = (idx >= 0 && idx < L_) ? xr[idx] : 0.f;
                }
            }
            float4 rA, rB;
            float* pA = (float*)&rA;
            float* pB = (float*)&rB;
            #pragma unroll
            for (int i = 0; i < 4; ++i) {
                float sA = s_bdwA[c], sB = s_bdwB[c];
                #pragma unroll
                for (int t = 0; t < 7; ++t) {
                    float xv = xw[i + t + 1];
                    sA = fmaf(xv, s_wdwA[c * 7 + t], sA);
                    sB = fmaf(xv, s_wdwB[c * 7 + t], sB);
                }
                pA[i] = sA; pB[i] = sB;
            }
            *(float4*)(dwAT + c * 64 + lbase) = rA;
            *(float4*)(dwBT + c * 64 + lbase) = rB;
        }
    }
    __syncthreads();

    // 1x1 conv -> off/msk, coalesced global write [b][k][l]
    if (tid < 192) {
        const int li = tid & 63;
        const int k  = tid >> 6;
        float oA = s_bpwA[k], oB = s_bpwB[k];
        const float* wA = s_wpwA + k * 64;
        const float* wB = s_wpwB + k * 64;
        #pragma unroll 8
        for (int c = 0; c < 64; ++c) {
            oA = fmaf(dwAT[c * 64 + li], wA[c], oA);
            oB = fmaf(dwBT[c * 64 + li], wB[c], oB);
        }
        long gi = ((long)(b * 3 + k)) * L_ + l0 + li;
        g_off[gi] = oA;
        g_msk[gi] = 1.f / (1.f + __expf(-oB));
    }
}

// ================= main kernel: gather + GEMM (split-k), 4 blocks/SM =====
// dynamic smem: 12288 floats (49152 B)
//   xv_d [0, 12288)  [ck][2*li] duplicated pairs (TLM_=32)
//   partial regions overlay after GEMM: p0 [0,2112), p1 [2112,4224)  [l][o] str 66
__global__ __launch_bounds__(NT_, 4) void main_kernel(
    const float* __restrict__ x,
    const float* __restrict__ bias,
    float* __restrict__ out)
{
    extern __shared__ float smem[];
    float* xv_d = smem;            // 12288 floats

    __shared__ float bias_s[64];

    const int tid = threadIdx.x;
    const int b   = blockIdx.y;
    const int l0  = blockIdx.x * TLM_;
    const float* xb = x + (long)b * 64 * L_;

    if (tid < 64) bias_s[tid] = bias[tid];

    // ---- gather + interp -> xv_d[ck][2*li] = (v, v) ----
    {
        const int li  = tid & 31;
        const int ck0 = tid >> 5;     // 0..7
        const float* offp = g_off + (long)b * 3 * L_ + l0 + li;
        const float* mskp = g_msk + (long)b * 3 * L_ + l0 + li;
        #pragma unroll 4
        for (int it = 0; it < 24; ++it) {
            int ck = it * 8 + ck0;
            int c  = ck & 63;
            int k  = ck >> 6;
            float off = __ldg(offp + k * L_);
            float m   = __ldg(mskp + k * L_);
            float p  = (float)(l0 + li - 1 + k) + off;
            float fi = floorf(p);
            float f  = p - fi;
            int i0 = (int)fi;
            int i1 = i0 + 1;
            const float* xr = xb + c * L_;
            float x0 = (i0 >= 0 && i0 < L_) ? __ldg(xr + i0) : 0.f;
            float x1 = (i1 >= 0 && i1 < L_) ? __ldg(xr + i1) : 0.f;
            float v = ((1.f - f) * x0 + f * x1) * m;
            *(float2*)&xv_d[ck * 64 + 2 * li] = make_float2(v, v);
        }
    }
    __syncthreads();

    // ---- GEMM: 2-way split-k; warp quadrant covers 32o x 16l ----
    // thread 4o x 4l; w = native o-pairs (1 LDG.128), x = dup pairs (2 LDS.128)
    const int warp  = tid >> 5;
    const int lane  = tid & 31;
    const int kg    = warp >> 2;          // ck half: 0 / 1
    const int q     = warp & 3;           // quadrant
    const int obase = (q & 1) * 32 + (lane & 7) * 4;
    const int lbase = (q >> 1) * 16 + (lane >> 3) * 4;

    unsigned long long acc[8];            // [p*4 + j]: o-pair p, l j
    #pragma unroll
    for (int i = 0; i < 8; ++i) acc[i] = 0ULL;

    const float* wp = g_wt + kg * 96 * 64 + obase;
    const float* xp = xv_d + kg * 96 * 64 + lbase * 2;

    #pragma unroll 4
    for (int ck = 0; ck < 96; ++ck) {
        float4 wv = __ldg((const float4*)wp);        wp += 64;
        ulonglong2 wu = *(ulonglong2*)&wv;           // native (o0,o1),(o2,o3)
        ulonglong2 x01 = *(const ulonglong2*)xp;     // (v0,v0),(v1,v1)
        ulonglong2 x23 = *(const ulonglong2*)(xp + 4);
        xp += 64;
        fma2(acc[0], wu.x, x01.x); fma2(acc[1], wu.x, x01.y);
        fma2(acc[2], wu.x, x23.x); fma2(acc[3], wu.x, x23.y);
        fma2(acc[4], wu.y, x01.x); fma2(acc[5], wu.y, x01.y);
        fma2(acc[6], wu.y, x23.x); fma2(acc[7], wu.y, x23.y);
    }
    __syncthreads();   // xv_d dead; both halves done

    // ---- write split-k partials: region kg, [l][o] stride PSTR_ ----
    {
        float* pr = smem + kg * 2112;
        #pragma unroll
        for (int p = 0; p < 2; ++p) {
            #pragma unroll
            for (int j = 0; j < 4; ++j) {
                float lo, hi;
                unpack2(acc[p * 4 + j], lo, hi);   // (o, o+1) at l = lbase+j
                *(float2*)&pr[(lbase + j) * PSTR_ + obase + p * 2] =
                    make_float2(lo, hi);
            }
        }
    }
    __syncthreads();

    // ---- reduce halves + bias + coalesced store ----
    {
        const int l  = tid & 31;
        const int o0 = tid >> 5;
        #pragma unroll
        for (int it = 0; it < 8; ++it) {
            int o = it * 8 + o0;
            float v = smem[l * PSTR_ + o] + smem[2112 + l * PSTR_ + o] + bias_s[o];
            out[((long)(b * 64 + o)) * L_ + l0 + l] = v;
        }
    }
}

// ================= host =================
extern "C" void kernel_launch(void* const* d_in, const int* in_sizes, int n_in,
                              void* d_out, int out_size) {
    const float* x      = (const float*)d_in[0];
    const float* wodw   = (const float*)d_in[1];
    const float* bodw   = (const float*)d_in[2];
    const float* wopw   = (const float*)d_in[3];
    const float* bopw   = (const float*)d_in[4];
    const float* wmdw   = (const float*)d_in[5];
    const float* bmdw   = (const float*)d_in[6];
    const float* wmpw   = (const float*)d_in[7];
    const float* bmpw   = (const float*)d_in[8];
    const float* weight = (const float*)d_in[9];
    const float* bias   = (const float*)d_in[10];
    float* out = (float*)d_out;

    wt_kernel<<<(CK_ * COUT_ + 255) / 256, 256>>>(weight);

    dim3 gridB(L_ / TLB_, B_);
    const int smem_b = 8192 * (int)sizeof(float);   // 32768 B
    cudaFuncSetAttribute(offmsk_kernel, cudaFuncAttributeMaxDynamicSharedMemorySize, smem_b);
    offmsk_kernel<<<gridB, NT_, smem_b>>>(x, wodw, bodw, wopw, bopw,
                                          wmdw, bmdw, wmpw, bmpw);

    dim3 gridM(L_ / TLM_, B_);
    const int smem_m = 12288 * (int)sizeof(float);  // 49152 B
    cudaFuncSetAttribute(main_kernel, cudaFuncAttributeMaxDynamicSharedMemorySize, smem_m);
    main_kernel<<<gridM, NT_, smem_m>>>(x, bias, out);
}